// round 3
// baseline (speedup 1.0000x reference)
#include <cuda_runtime.h>
#include <cuda_bf16.h>

#define HIDDEN 128
#define MAX_NODES 131072

__device__ float g_s1[MAX_NODES];
__device__ float g_s2[MAX_NODES];

// One warp per node: lane l loads x[node][4l..4l+3] and the matching W slices,
// computes partial dots for both halves of W, warp-reduces both at once.
__global__ void node_dot_kernel(const float4* __restrict__ x4,
                                const float4* __restrict__ W4,
                                int n_nodes,
                                float* __restrict__ s1,
                                float* __restrict__ s2) {
    int warp = (blockIdx.x * blockDim.x + threadIdx.x) >> 5;
    int lane = threadIdx.x & 31;
    if (warp >= n_nodes) return;

    float4 v  = x4[warp * 32 + lane];        // x row: 32 lanes * 4 = 128 floats
    float4 w1 = W4[lane];                    // W[0:128]
    float4 w2 = W4[32 + lane];               // W[128:256]

    float a = v.x * w1.x + v.y * w1.y + v.z * w1.z + v.w * w1.w;
    float c = v.x * w2.x + v.y * w2.y + v.z * w2.z + v.w * w2.w;

    #pragma unroll
    for (int o = 16; o > 0; o >>= 1) {
        a += __shfl_xor_sync(0xFFFFFFFFu, a, o);
        c += __shfl_xor_sync(0xFFFFFFFFu, c, o);
    }
    if (lane == 0) {
        s1[warp] = a;
        s2[warp] = c;
    }
}

// out[e] = s1[src[e]] + s2[dst[e]] + b.
// edge_index is int32 (2, n_edges). 4 edges per thread via int4 index loads.
__global__ void edge_kernel(const int* __restrict__ ei,
                            int n_edges,
                            const float* __restrict__ s1,
                            const float* __restrict__ s2,
                            const float* __restrict__ bptr,
                            float* __restrict__ out) {
    float b = __ldg(bptr);
    int tid = blockIdx.x * blockDim.x + threadIdx.x;
    int base = tid * 4;
    const int* src = ei;
    const int* dst = ei + n_edges;

    if (base + 3 < n_edges) {
        int4 s4 = *(const int4*)(src + base);
        int4 d4 = *(const int4*)(dst + base);
        float4 r;
        r.x = __ldg(&s1[s4.x]) + __ldg(&s2[d4.x]) + b;
        r.y = __ldg(&s1[s4.y]) + __ldg(&s2[d4.y]) + b;
        r.z = __ldg(&s1[s4.z]) + __ldg(&s2[d4.z]) + b;
        r.w = __ldg(&s1[s4.w]) + __ldg(&s2[d4.w]) + b;
        *(float4*)(out + base) = r;
    } else {
        for (int e = base; e < n_edges; e++) {
            out[e] = __ldg(&s1[src[e]]) + __ldg(&s2[dst[e]]) + b;
        }
    }
}

extern "C" void kernel_launch(void* const* d_in, const int* in_sizes, int n_in,
                              void* d_out, int out_size) {
    const float* x  = (const float*)d_in[0];   // (n_nodes, 128) f32
    const int*   ei = (const int*)d_in[1];     // (2, n_edges) int32
    const float* W  = (const float*)d_in[2];   // (1, 256) f32
    const float* b  = (const float*)d_in[3];   // (1,) f32
    float* out = (float*)d_out;

    int n_nodes = in_sizes[0] / HIDDEN;
    int n_edges = in_sizes[1] / 2;

    float* s1;
    float* s2;
    cudaGetSymbolAddress((void**)&s1, g_s1);
    cudaGetSymbolAddress((void**)&s2, g_s2);

    // Kernel 1: warp per node
    {
        int threads = 256;                     // 8 warps per block
        int warps_per_block = threads / 32;
        int blocks = (n_nodes + warps_per_block - 1) / warps_per_block;
        node_dot_kernel<<<blocks, threads>>>((const float4*)x, (const float4*)W,
                                             n_nodes, s1, s2);
    }

    // Kernel 2: streaming edge gather (4 edges/thread, int4 index loads)
    {
        int threads = 256;
        int edges_per_block = threads * 4;
        int blocks = (n_edges + edges_per_block - 1) / edges_per_block;
        edge_kernel<<<blocks, threads>>>(ei, n_edges, s1, s2, b, out);
    }
}

// round 5
// speedup vs baseline: 1.0982x; 1.0982x over previous
#include <cuda_runtime.h>
#include <cuda_bf16.h>

#define HIDDEN 128
#define MAX_NODES 131072

__device__ float g_s1[MAX_NODES];
__device__ float g_s2[MAX_NODES];

// Two nodes per warp: lane l loads x[2w][4l..] and x[2w+1][4l..] back-to-back
// (MLP=2), computes 4 partial dots, runs 4 independent shfl-reduction chains.
__global__ __launch_bounds__(256)
void node_dot_kernel(const float4* __restrict__ x4,
                     const float4* __restrict__ W4,
                     int n_nodes,
                     float* __restrict__ s1,
                     float* __restrict__ s2) {
    int warp = (blockIdx.x * blockDim.x + threadIdx.x) >> 5;
    int lane = threadIdx.x & 31;
    int n0 = warp * 2;
    if (n0 >= n_nodes) return;

    float4 w1 = W4[lane];        // W[0:128]   (L2/L1 resident)
    float4 w2 = W4[32 + lane];   // W[128:256]

    // Front-batch both row loads
    float4 v0 = x4[(size_t)n0 * 32 + lane];
    float4 v1;
    bool has1 = (n0 + 1) < n_nodes;
    if (has1) v1 = x4[(size_t)(n0 + 1) * 32 + lane];

    float a0 = v0.x * w1.x + v0.y * w1.y + v0.z * w1.z + v0.w * w1.w;
    float c0 = v0.x * w2.x + v0.y * w2.y + v0.z * w2.z + v0.w * w2.w;
    float a1 = 0.f, c1 = 0.f;
    if (has1) {
        a1 = v1.x * w1.x + v1.y * w1.y + v1.z * w1.z + v1.w * w1.w;
        c1 = v1.x * w2.x + v1.y * w2.y + v1.z * w2.z + v1.w * w2.w;
    }

    #pragma unroll
    for (int o = 16; o > 0; o >>= 1) {
        a0 += __shfl_xor_sync(0xFFFFFFFFu, a0, o);
        c0 += __shfl_xor_sync(0xFFFFFFFFu, c0, o);
        a1 += __shfl_xor_sync(0xFFFFFFFFu, a1, o);
        c1 += __shfl_xor_sync(0xFFFFFFFFu, c1, o);
    }
    if (lane == 0) {
        s1[n0] = a0;
        s2[n0] = c0;
        if (has1) {
            s1[n0 + 1] = a1;
            s2[n0 + 1] = c1;
        }
    }
}

// out[e] = s1[src[e]] + s2[dst[e]] + b.
// 8 edges per thread; all 16 gathers front-batched for max L1tex MLP.
__global__ __launch_bounds__(256)
void edge_kernel(const int* __restrict__ ei,
                 int n_edges,
                 const float* __restrict__ s1,
                 const float* __restrict__ s2,
                 const float* __restrict__ bptr,
                 float* __restrict__ out) {
    float b = __ldg(bptr);
    int tid = blockIdx.x * blockDim.x + threadIdx.x;
    int base = tid * 8;
    const int* src = ei;
    const int* dst = ei + n_edges;

    if (base + 7 < n_edges) {
        // Index loads (coalesced int4)
        int4 sa = *(const int4*)(src + base);
        int4 sb = *(const int4*)(src + base + 4);
        int4 da = *(const int4*)(dst + base);
        int4 db = *(const int4*)(dst + base + 4);

        // Front-batch all 16 gathers — independent, all outstanding together
        float v0 = __ldg(&s1[sa.x]);
        float v1 = __ldg(&s1[sa.y]);
        float v2 = __ldg(&s1[sa.z]);
        float v3 = __ldg(&s1[sa.w]);
        float v4 = __ldg(&s1[sb.x]);
        float v5 = __ldg(&s1[sb.y]);
        float v6 = __ldg(&s1[sb.z]);
        float v7 = __ldg(&s1[sb.w]);
        float u0 = __ldg(&s2[da.x]);
        float u1 = __ldg(&s2[da.y]);
        float u2 = __ldg(&s2[da.z]);
        float u3 = __ldg(&s2[da.w]);
        float u4 = __ldg(&s2[db.x]);
        float u5 = __ldg(&s2[db.y]);
        float u6 = __ldg(&s2[db.z]);
        float u7 = __ldg(&s2[db.w]);

        float4 r0 = make_float4(v0 + u0 + b, v1 + u1 + b, v2 + u2 + b, v3 + u3 + b);
        float4 r1 = make_float4(v4 + u4 + b, v5 + u5 + b, v6 + u6 + b, v7 + u7 + b);
        *(float4*)(out + base)     = r0;
        *(float4*)(out + base + 4) = r1;
    } else {
        for (int e = base; e < n_edges; e++) {
            out[e] = __ldg(&s1[src[e]]) + __ldg(&s2[dst[e]]) + b;
        }
    }
}

extern "C" void kernel_launch(void* const* d_in, const int* in_sizes, int n_in,
                              void* d_out, int out_size) {
    const float* x  = (const float*)d_in[0];   // (n_nodes, 128) f32
    const int*   ei = (const int*)d_in[1];     // (2, n_edges) int32
    const float* W  = (const float*)d_in[2];   // (1, 256) f32
    const float* b  = (const float*)d_in[3];   // (1,) f32
    float* out = (float*)d_out;

    int n_nodes = in_sizes[0] / HIDDEN;
    int n_edges = in_sizes[1] / 2;

    float* s1;
    float* s2;
    cudaGetSymbolAddress((void**)&s1, g_s1);
    cudaGetSymbolAddress((void**)&s2, g_s2);

    // Kernel 1: 2 nodes per warp
    {
        int threads = 256;                       // 8 warps per block
        int nodes_per_block = (threads / 32) * 2;  // 16
        int blocks = (n_nodes + nodes_per_block - 1) / nodes_per_block;
        node_dot_kernel<<<blocks, threads>>>((const float4*)x, (const float4*)W,
                                             n_nodes, s1, s2);
    }

    // Kernel 2: 8 edges per thread, front-batched gathers
    {
        int threads = 256;
        int edges_per_block = threads * 8;
        int blocks = (n_edges + edges_per_block - 1) / edges_per_block;
        edge_kernel<<<blocks, threads>>>(ei, n_edges, s1, s2, b, out);
    }
}